// round 5
// baseline (speedup 1.0000x reference)
#include <cuda_runtime.h>
#include <cstdint>

#define BATCH 64
#define S_LEN 2048
#define HID   256

// ---------------------------------------------------------------------------
// f32x2 packed-math helpers
// ---------------------------------------------------------------------------
__device__ __forceinline__ unsigned long long fma2(unsigned long long a,
                                                   unsigned long long b,
                                                   unsigned long long c) {
    unsigned long long d;
    asm("fma.rn.f32x2 %0, %1, %2, %3;" : "=l"(d) : "l"(a), "l"(b), "l"(c));
    return d;
}
__device__ __forceinline__ unsigned long long add2(unsigned long long a,
                                                   unsigned long long b) {
    unsigned long long d;
    asm("add.rn.f32x2 %0, %1, %2;" : "=l"(d) : "l"(a), "l"(b));
    return d;
}
__device__ __forceinline__ unsigned long long pack2(float x, float y) {
    unsigned long long r;
    asm("mov.b64 %0, {%1, %2};" : "=l"(r) : "f"(x), "f"(y));
    return r;
}
__device__ __forceinline__ float2 unpack2(unsigned long long v) {
    float2 r;
    asm("mov.b64 {%0, %1}, %2;" : "=f"(r.x), "=f"(r.y) : "l"(v));
    return r;
}
// fast tanh: (e^2x - 1) / (e^2x + 1), MUFU-based, abs err ~1e-6
__device__ __forceinline__ float tanh_fast(float x) {
    float xc = fminf(fmaxf(x, -15.0f), 15.0f);
    float ex;
    asm("ex2.approx.f32 %0, %1;" : "=f"(ex) : "f"(xc * 2.8853900817779268f));
    float rc;
    asm("rcp.approx.f32 %0, %1;" : "=f"(rc) : "f"(ex + 1.0f));
    return (ex - 1.0f) * rc;
}

// ---------------------------------------------------------------------------
// Kernel 1: xW = X @ W_ih^T   (131072x256 @ 256x256) fp32, written into d_out
// ---------------------------------------------------------------------------
__global__ void __launch_bounds__(256) xw_gemm(const float* __restrict__ X,
                                               const float* __restrict__ Wih,
                                               float* __restrict__ out) {
    __shared__ alignas(16) float Xs[32][68];
    __shared__ alignas(16) float Ws[32][68];

    const int tid = threadIdx.x;
    const int m0  = blockIdx.x * 64;
    const int h0  = blockIdx.y * 64;
    const int row = tid >> 2;
    const int c4  = tid & 3;
    const int tx  = tid & 15;
    const int ty  = tid >> 4;

    unsigned long long acc[4][2];
#pragma unroll
    for (int i = 0; i < 4; i++) { acc[i][0] = 0ull; acc[i][1] = 0ull; }

    const float* Xbase = X   + (size_t)(m0 + row) * 256;
    const float* Wbase = Wih + (size_t)(h0 + row) * 256;

    float4 xa = *(const float4*)(Xbase + 0  + c4 * 4);
    float4 xb = *(const float4*)(Xbase + 16 + c4 * 4);
    float4 wa = *(const float4*)(Wbase + 0  + c4 * 4);
    float4 wb = *(const float4*)(Wbase + 16 + c4 * 4);

#pragma unroll 1
    for (int k0 = 0; k0 < 256; k0 += 32) {
        __syncthreads();
#pragma unroll
        for (int e = 0; e < 4; e++) {
            Xs[c4 * 4 + e][row]      = (&xa.x)[e];
            Xs[16 + c4 * 4 + e][row] = (&xb.x)[e];
            Ws[c4 * 4 + e][row]      = (&wa.x)[e];
            Ws[16 + c4 * 4 + e][row] = (&wb.x)[e];
        }
        float4 nxa = make_float4(0, 0, 0, 0), nxb = nxa, nwa = nxa, nwb = nxa;
        if (k0 < 224) {
            nxa = *(const float4*)(Xbase + k0 + 32 + c4 * 4);
            nxb = *(const float4*)(Xbase + k0 + 48 + c4 * 4);
            nwa = *(const float4*)(Wbase + k0 + 32 + c4 * 4);
            nwb = *(const float4*)(Wbase + k0 + 48 + c4 * 4);
        }
        __syncthreads();

#pragma unroll
        for (int kk = 0; kk < 32; kk++) {
            float4 a4 = *(const float4*)(&Xs[kk][ty * 4]);
            const unsigned long long* bp =
                (const unsigned long long*)(&Ws[kk][tx * 4]);
            unsigned long long b0 = bp[0];
            unsigned long long b1 = bp[1];
            unsigned long long aa;
            aa = pack2(a4.x, a4.x);
            acc[0][0] = fma2(aa, b0, acc[0][0]); acc[0][1] = fma2(aa, b1, acc[0][1]);
            aa = pack2(a4.y, a4.y);
            acc[1][0] = fma2(aa, b0, acc[1][0]); acc[1][1] = fma2(aa, b1, acc[1][1]);
            aa = pack2(a4.z, a4.z);
            acc[2][0] = fma2(aa, b0, acc[2][0]); acc[2][1] = fma2(aa, b1, acc[2][1]);
            aa = pack2(a4.w, a4.w);
            acc[3][0] = fma2(aa, b0, acc[3][0]); acc[3][1] = fma2(aa, b1, acc[3][1]);
        }
        xa = nxa; xb = nxb; wa = nwa; wb = nwb;
    }

#pragma unroll
    for (int i = 0; i < 4; i++) {
        float2 p = unpack2(acc[i][0]);
        float2 q = unpack2(acc[i][1]);
        float4 v = make_float4(p.x, p.y, q.x, q.y);
        *(float4*)(out + (size_t)(m0 + ty * 4 + i) * 256 + h0 + tx * 4) = v;
    }
}

// ---------------------------------------------------------------------------
// Kernel 2 (v5): recurrence, one CTA per batch, k-split thread pairs.
// Thread (i = t&127, half = t>>7) computes PARTIALS of outputs {2i, 2i+1}
// over k in [128*half, 128*half+128):
//   - each h LDS.128 (broadcast) feeds BOTH outputs  -> h traffic halved
//   - W: 48 pairs/output in registers (192 floats), 16 pairs/output in smem
//     as ulonglong2 [q][t] (LDS.128, lane-distinct, conflict-free)
// Partials combine CTA-locally: STS.64 -> bar -> finalize thread t does one
// LDS.128, fast-tanh, STS h, STG out -> bar.
// ---------------------------------------------------------------------------
__global__ void __launch_bounds__(256, 1)
rnn_scan(const float* __restrict__ Whh, float* __restrict__ io,
         float* __restrict__ hn) {
    extern __shared__ ulonglong2 Wt[];               // [16][256]: q<8 -> o0, q>=8 -> o1
    __shared__ alignas(16) float  hbuf[2][HID];      // double-buffered h
    __shared__ alignas(16) float2 part2[128][2];     // [i][half] = (pA, pB)

    const int t = threadIdx.x;
    const int b = blockIdx.x;
    const int i = t & 127;
    const int half = t >> 7;
    const int o0 = 2 * i;
    const int o1 = 2 * i + 1;

    // ---- load W: per output 48 reg-pairs + 8 smem ulonglong2 (16 pairs) ----
    unsigned long long w[96];
    {
        const float4* r0 = (const float4*)(Whh + (size_t)o0 * 256 + half * 128);
        const float4* r1 = (const float4*)(Whh + (size_t)o1 * 256 + half * 128);
#pragma unroll
        for (int j = 0; j < 24; j++) {
            float4 f = r0[j];
            w[2 * j]     = pack2(f.x, f.y);
            w[2 * j + 1] = pack2(f.z, f.w);
        }
#pragma unroll
        for (int j = 0; j < 24; j++) {
            float4 f = r1[j];
            w[48 + 2 * j]     = pack2(f.x, f.y);
            w[48 + 2 * j + 1] = pack2(f.z, f.w);
        }
#pragma unroll
        for (int q = 0; q < 8; q++) {
            float4 f = r0[24 + q];
            ulonglong2 u; u.x = pack2(f.x, f.y); u.y = pack2(f.z, f.w);
            Wt[q * 256 + t] = u;
        }
#pragma unroll
        for (int q = 0; q < 8; q++) {
            float4 f = r1[24 + q];
            ulonglong2 u; u.x = pack2(f.x, f.y); u.y = pack2(f.z, f.w);
            Wt[(8 + q) * 256 + t] = u;
        }
    }

    hbuf[0][t] = 0.0f;   // h0 = 0
    __syncthreads();

    float* xcol = io + (size_t)b * S_LEN * HID + t;   // column t, stride HID
    float xw0 = xcol[0];
    float xw1 = xcol[HID];

    const int ii = t >> 1;     // finalize indices
    const int cc = t & 1;

    for (int s = 0; s < S_LEN; s++) {
        // h slice for this k-half: 32 broadcast LDS.128 feed both outputs
        const ulonglong2* h2 =
            (const ulonglong2*)hbuf[s & 1] + half * 32;

        unsigned long long a0 = 0ull, a1 = 0ull, b0 = 0ull, b1 = 0ull;
#pragma unroll
        for (int j = 0; j < 24; j++) {          // reg W: pairs 0..47
            ulonglong2 v = h2[j];
            a0 = fma2(w[2 * j],          v.x, a0);
            a1 = fma2(w[2 * j + 1],      v.y, a1);
            b0 = fma2(w[48 + 2 * j],     v.x, b0);
            b1 = fma2(w[48 + 2 * j + 1], v.y, b1);
        }
#pragma unroll
        for (int q = 0; q < 8; q++) {           // smem W: pairs 48..63
            ulonglong2 v  = h2[24 + q];
            ulonglong2 wa = Wt[q * 256 + t];
            ulonglong2 wb = Wt[(8 + q) * 256 + t];
            a0 = fma2(wa.x, v.x, a0);
            a1 = fma2(wa.y, v.y, a1);
            b0 = fma2(wb.x, v.x, b0);
            b1 = fma2(wb.y, v.y, b1);
        }
        a0 = add2(a0, a1);
        b0 = add2(b0, b1);
        float2 pa = unpack2(a0);
        float2 pb = unpack2(b0);
        part2[i][half] = make_float2(pa.x + pa.y, pb.x + pb.y);

        __syncthreads();   // partials ready

        // finalize output o = t
        float4 q4 = *(const float4*)&part2[ii][0];
        float lo = cc ? q4.y : q4.x;     // half-0 partial of output t
        float hi = cc ? q4.w : q4.z;     // half-1 partial of output t
        float v = tanh_fast(lo + hi + xw0);

        hbuf[(s + 1) & 1][t] = v;
        xcol[(size_t)s * HID] = v;
        if (s == S_LEN - 1) hn[(size_t)b * HID + t] = v;

        xw0 = xw1;
        xw1 = (s + 2 < S_LEN) ? xcol[(size_t)(s + 2) * HID] : 0.0f;

        __syncthreads();   // h(s) + part WAR before next step
    }
}

// ---------------------------------------------------------------------------
extern "C" void kernel_launch(void* const* d_in, const int* in_sizes, int n_in,
                              void* d_out, int out_size) {
    (void)in_sizes; (void)n_in; (void)out_size;
    const float* x   = (const float*)d_in[0];  // [64, 2048, 256]
    const float* wih = (const float*)d_in[1];  // [256, 256]
    const float* whh = (const float*)d_in[2];  // [256, 256]
    float* out = (float*)d_out;                           // output [64,2048,256]
    float* hn  = out + (size_t)BATCH * S_LEN * HID;       // h_n [1,64,256]

    dim3 grid_gemm(BATCH * S_LEN / 64, HID / 64);
    xw_gemm<<<grid_gemm, 256>>>(x, wih, out);

    const int smem_bytes = 16 * 256 * (int)sizeof(ulonglong2);  // 64 KB
    cudaFuncSetAttribute(rnn_scan,
                         cudaFuncAttributeMaxDynamicSharedMemorySize,
                         smem_bytes);
    rnn_scan<<<BATCH, 256, smem_bytes>>>(whh, out, hn);
}

// round 6
// speedup vs baseline: 1.4411x; 1.4411x over previous
#include <cuda_runtime.h>
#include <cstdint>

#define BATCH 64
#define S_LEN 2048
#define HID   256

// ---------------------------------------------------------------------------
// f32x2 packed-math helpers
// ---------------------------------------------------------------------------
__device__ __forceinline__ unsigned long long fma2(unsigned long long a,
                                                   unsigned long long b,
                                                   unsigned long long c) {
    unsigned long long d;
    asm("fma.rn.f32x2 %0, %1, %2, %3;" : "=l"(d) : "l"(a), "l"(b), "l"(c));
    return d;
}
__device__ __forceinline__ unsigned long long add2(unsigned long long a,
                                                   unsigned long long b) {
    unsigned long long d;
    asm("add.rn.f32x2 %0, %1, %2;" : "=l"(d) : "l"(a), "l"(b));
    return d;
}
__device__ __forceinline__ unsigned long long pack2(float x, float y) {
    unsigned long long r;
    asm("mov.b64 %0, {%1, %2};" : "=l"(r) : "f"(x), "f"(y));
    return r;
}
__device__ __forceinline__ float2 unpack2(unsigned long long v) {
    float2 r;
    asm("mov.b64 {%0, %1}, %2;" : "=f"(r.x), "=f"(r.y) : "l"(v));
    return r;
}
// fast tanh: (e^2x - 1) / (e^2x + 1), MUFU-based, abs err ~1e-6
__device__ __forceinline__ float tanh_fast(float x) {
    float xc = fminf(fmaxf(x, -15.0f), 15.0f);
    float ex;
    asm("ex2.approx.f32 %0, %1;" : "=f"(ex) : "f"(xc * 2.8853900817779268f));
    float rc;
    asm("rcp.approx.f32 %0, %1;" : "=f"(rc) : "f"(ex + 1.0f));
    return (ex - 1.0f) * rc;
}

// ---------------------------------------------------------------------------
// Kernel 1: xW = X @ W_ih^T   (131072x256 @ 256x256) fp32, written into d_out
// ---------------------------------------------------------------------------
__global__ void __launch_bounds__(256) xw_gemm(const float* __restrict__ X,
                                               const float* __restrict__ Wih,
                                               float* __restrict__ out) {
    __shared__ alignas(16) float Xs[32][68];
    __shared__ alignas(16) float Ws[32][68];

    const int tid = threadIdx.x;
    const int m0  = blockIdx.x * 64;
    const int h0  = blockIdx.y * 64;
    const int row = tid >> 2;
    const int c4  = tid & 3;
    const int tx  = tid & 15;
    const int ty  = tid >> 4;

    unsigned long long acc[4][2];
#pragma unroll
    for (int i = 0; i < 4; i++) { acc[i][0] = 0ull; acc[i][1] = 0ull; }

    const float* Xbase = X   + (size_t)(m0 + row) * 256;
    const float* Wbase = Wih + (size_t)(h0 + row) * 256;

    float4 xa = *(const float4*)(Xbase + 0  + c4 * 4);
    float4 xb = *(const float4*)(Xbase + 16 + c4 * 4);
    float4 wa = *(const float4*)(Wbase + 0  + c4 * 4);
    float4 wb = *(const float4*)(Wbase + 16 + c4 * 4);

#pragma unroll 1
    for (int k0 = 0; k0 < 256; k0 += 32) {
        __syncthreads();
#pragma unroll
        for (int e = 0; e < 4; e++) {
            Xs[c4 * 4 + e][row]      = (&xa.x)[e];
            Xs[16 + c4 * 4 + e][row] = (&xb.x)[e];
            Ws[c4 * 4 + e][row]      = (&wa.x)[e];
            Ws[16 + c4 * 4 + e][row] = (&wb.x)[e];
        }
        float4 nxa = make_float4(0, 0, 0, 0), nxb = nxa, nwa = nxa, nwb = nxa;
        if (k0 < 224) {
            nxa = *(const float4*)(Xbase + k0 + 32 + c4 * 4);
            nxb = *(const float4*)(Xbase + k0 + 48 + c4 * 4);
            nwa = *(const float4*)(Wbase + k0 + 32 + c4 * 4);
            nwb = *(const float4*)(Wbase + k0 + 48 + c4 * 4);
        }
        __syncthreads();

#pragma unroll
        for (int kk = 0; kk < 32; kk++) {
            float4 a4 = *(const float4*)(&Xs[kk][ty * 4]);
            const unsigned long long* bp =
                (const unsigned long long*)(&Ws[kk][tx * 4]);
            unsigned long long b0 = bp[0];
            unsigned long long b1 = bp[1];
            unsigned long long aa;
            aa = pack2(a4.x, a4.x);
            acc[0][0] = fma2(aa, b0, acc[0][0]); acc[0][1] = fma2(aa, b1, acc[0][1]);
            aa = pack2(a4.y, a4.y);
            acc[1][0] = fma2(aa, b0, acc[1][0]); acc[1][1] = fma2(aa, b1, acc[1][1]);
            aa = pack2(a4.z, a4.z);
            acc[2][0] = fma2(aa, b0, acc[2][0]); acc[2][1] = fma2(aa, b1, acc[2][1]);
            aa = pack2(a4.w, a4.w);
            acc[3][0] = fma2(aa, b0, acc[3][0]); acc[3][1] = fma2(aa, b1, acc[3][1]);
        }
        xa = nxa; xb = nxb; wa = nwa; wb = nwb;
    }

#pragma unroll
    for (int i = 0; i < 4; i++) {
        float2 p = unpack2(acc[i][0]);
        float2 q = unpack2(acc[i][1]);
        float4 v = make_float4(p.x, p.y, q.x, q.y);
        *(float4*)(out + (size_t)(m0 + ty * 4 + i) * 256 + h0 + tx * 4) = v;
    }
}

// ---------------------------------------------------------------------------
// Kernel 2 (v6): recurrence, one CTA per batch, pair-in-warp k-split.
// Thread t: pair i = t>>1, half = t&1; computes PARTIALS of outputs
// {t&~1, t|1} over k in [128*half, +128). Adjacent lanes are the two k-halves
// of the same output pair -> combine via 2x shfl.xor(1), no smem round-trip,
// no second barrier. Each h LDS.128 feeds both outputs (h traffic halved vs
// v4); h array padded 16B at the k=128 boundary so even/odd-lane broadcast
// addresses hit disjoint banks. W: 48 reg-pairs per output + 8 smem
// ulonglong2 per output (lane-distinct LDS.128, conflict-free). One
// __syncthreads per step. Fast MUFU tanh.
// ---------------------------------------------------------------------------
__global__ void __launch_bounds__(256, 1)
rnn_scan(const float* __restrict__ Whh, float* __restrict__ io,
         float* __restrict__ hn) {
    extern __shared__ ulonglong2 Wt[];            // [16][256]: q<8 -> o0, q>=8 -> o1
    __shared__ alignas(16) float hbuf[2][264];    // padded: k -> k + 4*(k>>7)

    const int t = threadIdx.x;
    const int b = blockIdx.x;
    const int half = t & 1;                 // k-half this thread covers
    const int o0 = t & ~1;                  // even output of the pair
    const int o1 = t | 1;                   // odd output of the pair
    const int hidx = t + 4 * (t >> 7);      // padded h index for write (o = t)

    // ---- load W: per output 48 reg ull (96 floats) + 8 smem ulonglong2 ----
    unsigned long long w[96];
    {
        const float4* r0 = (const float4*)(Whh + (size_t)o0 * 256 + half * 128);
        const float4* r1 = (const float4*)(Whh + (size_t)o1 * 256 + half * 128);
#pragma unroll
        for (int j = 0; j < 24; j++) {
            float4 f = r0[j];
            w[2 * j]     = pack2(f.x, f.y);
            w[2 * j + 1] = pack2(f.z, f.w);
        }
#pragma unroll
        for (int j = 0; j < 24; j++) {
            float4 f = r1[j];
            w[48 + 2 * j]     = pack2(f.x, f.y);
            w[48 + 2 * j + 1] = pack2(f.z, f.w);
        }
#pragma unroll
        for (int q = 0; q < 8; q++) {
            float4 f = r0[24 + q];
            ulonglong2 u; u.x = pack2(f.x, f.y); u.y = pack2(f.z, f.w);
            Wt[q * 256 + t] = u;
        }
#pragma unroll
        for (int q = 0; q < 8; q++) {
            float4 f = r1[24 + q];
            ulonglong2 u; u.x = pack2(f.x, f.y); u.y = pack2(f.z, f.w);
            Wt[(8 + q) * 256 + t] = u;
        }
    }

    hbuf[0][hidx] = 0.0f;   // h0 = 0
    __syncthreads();

    float* xcol = io + (size_t)b * S_LEN * HID + t;   // output column o = t
    float xw0 = xcol[0];
    float xw1 = xcol[HID];
    float v = 0.0f;

    for (int s = 0; s < S_LEN; s++) {
        // h slice for this k-half: 33 ulonglong2 stride covers the 16B pad
        const ulonglong2* h2 = (const ulonglong2*)hbuf[s & 1] + half * 33;

        unsigned long long a0 = 0ull, a1 = 0ull, b0 = 0ull, b1 = 0ull;
#pragma unroll
        for (int j = 0; j < 24; j++) {          // reg W: k-pairs 0..47
            ulonglong2 hv = h2[j];
            a0 = fma2(w[2 * j],          hv.x, a0);
            a1 = fma2(w[2 * j + 1],      hv.y, a1);
            b0 = fma2(w[48 + 2 * j],     hv.x, b0);
            b1 = fma2(w[48 + 2 * j + 1], hv.y, b1);
        }
#pragma unroll
        for (int q = 0; q < 8; q++) {           // smem W: k-pairs 48..63
            ulonglong2 hv = h2[24 + q];
            ulonglong2 wa = Wt[q * 256 + t];
            ulonglong2 wb = Wt[(8 + q) * 256 + t];
            a0 = fma2(wa.x, hv.x, a0);
            a1 = fma2(wa.y, hv.y, a1);
            b0 = fma2(wb.x, hv.x, b0);
            b1 = fma2(wb.y, hv.y, b1);
        }
        a0 = add2(a0, a1);
        b0 = add2(b0, b1);
        float2 pa2 = unpack2(a0);
        float2 pb2 = unpack2(b0);
        float pa = pa2.x + pa2.y;               // partial of o0 (this k-half)
        float pb = pb2.x + pb2.y;               // partial of o1 (this k-half)

        // combine with partner lane (other k-half), no smem, no extra barrier
        float ra = __shfl_xor_sync(0xffffffffu, pa, 1);
        float rb = __shfl_xor_sync(0xffffffffu, pb, 1);
        float total = half ? (pb + rb) : (pa + ra);   // full dot for output t

        v = tanh_fast(total + xw0);

        hbuf[(s + 1) & 1][hidx] = v;            // next step's h
        xcol[(size_t)s * HID] = v;              // output[b][s][t] (in place)

        xw0 = xw1;
        xw1 = (s + 2 < S_LEN) ? xcol[(size_t)(s + 2) * HID] : 0.0f;

        __syncthreads();                        // h(s) visible before s+1 reads
    }

    hn[(size_t)b * HID + t] = v;                // h_n = h(S_LEN-1)
}

// ---------------------------------------------------------------------------
extern "C" void kernel_launch(void* const* d_in, const int* in_sizes, int n_in,
                              void* d_out, int out_size) {
    (void)in_sizes; (void)n_in; (void)out_size;
    const float* x   = (const float*)d_in[0];  // [64, 2048, 256]
    const float* wih = (const float*)d_in[1];  // [256, 256]
    const float* whh = (const float*)d_in[2];  // [256, 256]
    float* out = (float*)d_out;                           // output [64,2048,256]
    float* hn  = out + (size_t)BATCH * S_LEN * HID;       // h_n [1,64,256]

    dim3 grid_gemm(BATCH * S_LEN / 64, HID / 64);
    xw_gemm<<<grid_gemm, 256>>>(x, wih, out);

    const int smem_bytes = 16 * 256 * (int)sizeof(ulonglong2);  // 64 KB
    cudaFuncSetAttribute(rnn_scan,
                         cudaFuncAttributeMaxDynamicSharedMemorySize,
                         smem_bytes);
    rnn_scan<<<BATCH, 256, smem_bytes>>>(whh, out, hn);
}